// round 4
// baseline (speedup 1.0000x reference)
#include <cuda_runtime.h>

// NCA grow step, fused:
//  Kernel A (nca_update): perceive (depthwise 3x3: id/sobelx/sobely/laplace)
//    -> MLP 64->128 (relu) -> 128->16 -> x_new = x + dx*fire. Writes x_new to
//    d_out and x_new alpha (ch 3) to g_alpha scratch.
//  Kernel B (nca_life): life = (maxpool3(x.ch3)>0.1) & (maxpool3(x_new.ch3)>0.1);
//    zeroes d_out pixels where !life (x_new already stored where life).
//
// R3 root cause fixed: w1s was declared [2048] but indexed to [4095]
// (w1 = 128 rows x 32 f32x2 pairs = 4096 pairs) -> 16KB shared overrun ->
// illegal memory access. Now correctly sized at 4096.

typedef unsigned long long ULL;

#define HW 65536  // 256*256

__device__ float g_alpha[16 * HW];  // x_new alpha channel scratch (4 MB)

__device__ __forceinline__ ULL pack2(float lo, float hi) {
    ULL r;
    asm("mov.b64 %0, {%1, %2};" : "=l"(r) : "f"(lo), "f"(hi));
    return r;
}
__device__ __forceinline__ void unpack2(float& lo, float& hi, ULL v) {
    asm("mov.b64 {%0, %1}, %2;" : "=f"(lo), "=f"(hi) : "l"(v));
}
__device__ __forceinline__ ULL fma2(ULL a, ULL b, ULL c) {
    ULL d;
    asm("fma.rn.f32x2 %0, %1, %2, %3;" : "=l"(d) : "l"(a), "l"(b), "l"(c));
    return d;
}
__device__ __forceinline__ ULL add2(ULL a, ULL b) {
    ULL d;
    asm("add.rn.f32x2 %0, %1, %2;" : "=l"(d) : "l"(a), "l"(b));
    return d;
}

__global__ void __launch_bounds__(256, 2) nca_update_kernel(
    const float* __restrict__ x, const float* __restrict__ rmask,
    const float* __restrict__ w1, const float* __restrict__ b1,
    const float* __restrict__ w2, float* __restrict__ out)
{
    __shared__ __align__(16) ULL w1s[4096];   // [128 o][32 pairs of i]  (32 KB)
    __shared__ __align__(16) ULL w2ts[1024];  // [128 o][8 pairs of out-c] (8 KB)
    __shared__ float b1s[128];

    const int tid = threadIdx.x;

    // Stage weights. w1 [128,64] row-major: consecutive i are contiguous -> free pairing.
    const ULL* w1u = reinterpret_cast<const ULL*>(w1);
    for (int i = tid; i < 4096; i += 256) w1s[i] = w1u[i];
    if (tid < 128) b1s[tid] = b1[tid];
    // w2 [16,128]: transpose to [o][c] and pair along output c.
    for (int i = tid; i < 1024; i += 256) {
        int o = i >> 3, j = i & 7;
        w2ts[i] = pack2(w2[(2 * j) * 128 + o], w2[(2 * j + 1) * 128 + o]);
    }
    __syncthreads();

    const int w = tid;
    const int h = blockIdx.x;
    const int b = blockIdx.y;
    const int pid = h * 256 + w;
    const bool hm = h > 0, hp = h < 255, wm = w > 0, wp = w < 255;

    // Hoist the fire mask load: overlaps DRAM latency with the MLP below.
    const float rmv = __ldg(rmask + (size_t)b * HW + pid);

    // ---- Perceive: y[64] packed as 32 x f32x2: (id,sx),(sy,lap) per channel ----
    ULL y2[32];
#pragma unroll
    for (int c = 0; c < 16; c++) {
        const float* xc = x + (size_t)(b * 16 + c) * HW + pid;
        float v00 = (hm && wm) ? __ldg(xc - 257) : 0.f;
        float v01 = hm         ? __ldg(xc - 256) : 0.f;
        float v02 = (hm && wp) ? __ldg(xc - 255) : 0.f;
        float v10 = wm         ? __ldg(xc - 1)   : 0.f;
        float v11 =              __ldg(xc);
        float v12 = wp         ? __ldg(xc + 1)   : 0.f;
        float v20 = (hp && wm) ? __ldg(xc + 255) : 0.f;
        float v21 = hp         ? __ldg(xc + 256) : 0.f;
        float v22 = (hp && wp) ? __ldg(xc + 257) : 0.f;
        float sx  = ((v02 - v00) + 2.f * (v12 - v10) + (v22 - v20)) * 0.125f;
        float sy  = ((v20 - v00) + 2.f * (v21 - v01) + (v22 - v02)) * 0.125f;
        float lap = v01 + v10 + v12 + v21 - 4.f * v11;
        y2[2 * c]     = pack2(v11, sx);
        y2[2 * c + 1] = pack2(sy, lap);
    }

    // ---- MLP: 64 -> 128 (relu) -> 16, all in packed f32x2 ----
    ULL dx2[8];
#pragma unroll
    for (int j = 0; j < 8; j++) dx2[j] = 0ULL;  // bit pattern 0 == (0.f, 0.f)

    // 4 independent accumulator chains per o-iteration (4-way ILP); unroll 2
    // lets the scheduler interleave adjacent o for extra slack.
#pragma unroll 2
    for (int o = 0; o < 128; o++) {
        const ulonglong2* row = reinterpret_cast<const ulonglong2*>(&w1s[o * 32]);
        ULL a0 = 0ULL, a1 = 0ULL, a2 = 0ULL, a3 = 0ULL;
#pragma unroll
        for (int i = 0; i < 8; i++) {
            ulonglong2 q0 = row[2 * i];
            ulonglong2 q1 = row[2 * i + 1];
            a0 = fma2(q0.x, y2[4 * i + 0], a0);
            a1 = fma2(q0.y, y2[4 * i + 1], a1);
            a2 = fma2(q1.x, y2[4 * i + 2], a2);
            a3 = fma2(q1.y, y2[4 * i + 3], a3);
        }
        ULL s = add2(add2(a0, a1), add2(a2, a3));
        float slo, shi;
        unpack2(slo, shi, s);
        float hv = fmaxf(slo + shi + b1s[o], 0.f);
        ULL hp2 = pack2(hv, hv);
        const ulonglong2* wr = reinterpret_cast<const ulonglong2*>(&w2ts[o * 8]);
#pragma unroll
        for (int j = 0; j < 4; j++) {
            ulonglong2 q = wr[j];
            dx2[2 * j]     = fma2(q.x, hp2, dx2[2 * j]);
            dx2[2 * j + 1] = fma2(q.y, hp2, dx2[2 * j + 1]);
        }
    }

    // ---- Stochastic update + store x_new ----
    const float fire = (rmv <= 0.5f) ? 1.f : 0.f;
#pragma unroll
    for (int j = 0; j < 8; j++) {
        float d0, d1;
        unpack2(d0, d1, dx2[j]);
        int ch0 = 2 * j, ch1 = 2 * j + 1;
        float cen0, cen1, t;
        unpack2(cen0, t, y2[2 * ch0]);  // identity filter = x center value
        unpack2(cen1, t, y2[2 * ch1]);
        float xn0 = cen0 + d0 * fire;
        float xn1 = cen1 + d1 * fire;
        out[(size_t)(b * 16 + ch0) * HW + pid] = xn0;
        out[(size_t)(b * 16 + ch1) * HW + pid] = xn1;
        if (j == 1)  // ch1 == 3: alpha channel of x_new
            g_alpha[(size_t)b * HW + pid] = xn1;
    }
}

__global__ void __launch_bounds__(256) nca_life_kernel(
    const float* __restrict__ x, float* __restrict__ out)
{
    const int w = threadIdx.x;
    const int h = blockIdx.x;
    const int b = blockIdx.y;
    const int pid = h * 256 + w;

    const float* x3 = x + (size_t)(b * 16 + 3) * HW;
    const float* al = g_alpha + (size_t)b * HW;

    float pre = -1e30f, post = -1e30f;
#pragma unroll
    for (int dh = -1; dh <= 1; dh++) {
        int hh = h + dh;
        if (hh < 0 || hh > 255) continue;
#pragma unroll
        for (int dw = -1; dw <= 1; dw++) {
            int ww = w + dw;
            if (ww < 0 || ww > 255) continue;
            int q = hh * 256 + ww;
            pre  = fmaxf(pre,  __ldg(x3 + q));
            post = fmaxf(post, al[q]);
        }
    }

    // life = pre & post. Where life, out already holds x_new -> only write zeros.
    if (!(pre > 0.1f && post > 0.1f)) {
#pragma unroll
        for (int c = 0; c < 16; c++)
            out[(size_t)(b * 16 + c) * HW + pid] = 0.f;
    }
}

extern "C" void kernel_launch(void* const* d_in, const int* in_sizes, int n_in,
                              void* d_out, int out_size)
{
    // Bind inputs by element count — all five are distinct:
    //   x:         16*16*256*256 = 16777216
    //   rand_mask: 16*1*256*256  =  1048576
    //   w1:        128*64        =     8192
    //   w2:        16*128        =     2048
    //   b1:        128
    const float* x  = nullptr;
    const float* rm = nullptr;
    const float* w1 = nullptr;
    const float* b1 = nullptr;
    const float* w2 = nullptr;
    for (int i = 0; i < n_in; i++) {
        switch (in_sizes[i]) {
            case 16777216: x  = (const float*)d_in[i]; break;
            case 1048576:  rm = (const float*)d_in[i]; break;
            case 8192:     w1 = (const float*)d_in[i]; break;
            case 2048:     w2 = (const float*)d_in[i]; break;
            case 128:      b1 = (const float*)d_in[i]; break;
            default: break;
        }
    }
    float* out = (float*)d_out;  // [16,16,256,256]

    dim3 grid(256, 16);
    nca_update_kernel<<<grid, 256>>>(x, rm, w1, b1, w2, out);
    nca_life_kernel<<<grid, 256>>>(x, out);
}

// round 9
// speedup vs baseline: 1.3347x; 1.3347x over previous
#include <cuda_runtime.h>
#include <cstdint>

// NCA grow step — fire-sparsity compaction (sm_100 scalar FFMA roofline / 2).
//
//  zero:  reset compaction counter (graph-replay safe).
//  prep:  fire = rand_mask <= 0.5. Non-fired pixels: x_new = x -> out + alpha.
//         Fired pixels: ballot-compacted into g_list (exactly ~50% of 1M).
//  mlp:   grid-stride over g_list with FULL warps: perceive (depthwise 3x3)
//         -> MLP 64->128 relu -> 128->16 -> x_new = x + dx -> out + alpha.
//  life:  life = (maxpool3(x.a)>0.1)&(maxpool3(x_new.a)>0.1); zero dead pixels.
//
// R4 dense kernel measured 677.9us = scalar-FFMA roofline; halving FMA work via
// compaction targets ~355us. (tcgen05 unavailable: harness builds compute_100
// without the 'a' suffix — R6 ptxas rejected all tcgen05/.kind::tf32.)

typedef unsigned long long ULL;

#define HW 65536  // 256*256

__device__ float g_alpha[16 * HW];   // x_new alpha scratch (4 MB)
__device__ int   g_list[16 * HW];    // fired pixel ids: b*65536 + pid (4 MB)
__device__ int   g_count;

__device__ __forceinline__ ULL pack2(float lo, float hi) {
    ULL r;
    asm("mov.b64 %0, {%1, %2};" : "=l"(r) : "f"(lo), "f"(hi));
    return r;
}
__device__ __forceinline__ void unpack2(float& lo, float& hi, ULL v) {
    asm("mov.b64 {%0, %1}, %2;" : "=f"(lo), "=f"(hi) : "l"(v));
}
__device__ __forceinline__ ULL fma2(ULL a, ULL b, ULL c) {
    ULL d;
    asm("fma.rn.f32x2 %0, %1, %2, %3;" : "=l"(d) : "l"(a), "l"(b), "l"(c));
    return d;
}
__device__ __forceinline__ ULL add2(ULL a, ULL b) {
    ULL d;
    asm("add.rn.f32x2 %0, %1, %2;" : "=l"(d) : "l"(a), "l"(b));
    return d;
}

__global__ void nca_zero_kernel() { g_count = 0; }

// ---- prep: handle non-fired pixels, compact fired pixel ids ----
__global__ void __launch_bounds__(256) nca_prep_kernel(
    const float* __restrict__ x, const float* __restrict__ rmask,
    float* __restrict__ out)
{
    const int w = threadIdx.x;
    const int h = blockIdx.x;
    const int b = blockIdx.y;
    const int pid = h * 256 + w;
    const int lane = w & 31;

    const bool fire = __ldg(rmask + (size_t)b * HW + pid) <= 0.5f;

    unsigned m = __ballot_sync(0xffffffffu, fire);
    int base = 0;
    if (lane == 0) base = atomicAdd(&g_count, __popc(m));
    base = __shfl_sync(0xffffffffu, base, 0);
    if (fire) {
        g_list[base + __popc(m & ((1u << lane) - 1u))] = b * HW + pid;
    } else {
        // x_new = x: copy through, record alpha
#pragma unroll
        for (int c = 0; c < 16; c++) {
            float v = __ldg(x + (size_t)(b * 16 + c) * HW + pid);
            out[(size_t)(b * 16 + c) * HW + pid] = v;
            if (c == 3) g_alpha[(size_t)b * HW + pid] = v;
        }
    }
}

// ---- mlp: full-warp work on fired pixels only ----
#define MLP_BLOCKS 1024

__global__ void __launch_bounds__(256, 2) nca_mlp_kernel(
    const float* __restrict__ x,
    const float* __restrict__ w1, const float* __restrict__ b1,
    const float* __restrict__ w2, float* __restrict__ out)
{
    __shared__ __align__(16) ULL w1s[4096];   // [128 o][32 pairs of i]  (32 KB)
    __shared__ __align__(16) ULL w2ts[1024];  // [128 o][8 pairs of out-c] (8 KB)
    __shared__ float b1s[128];

    const int tid = threadIdx.x;

    const ULL* w1u = reinterpret_cast<const ULL*>(w1);
    for (int i = tid; i < 4096; i += 256) w1s[i] = w1u[i];
    if (tid < 128) b1s[tid] = b1[tid];
    for (int i = tid; i < 1024; i += 256) {
        int o = i >> 3, j = i & 7;
        w2ts[i] = pack2(w2[(2 * j) * 128 + o], w2[(2 * j + 1) * 128 + o]);
    }
    __syncthreads();

    const int count = g_count;

    for (int idx = blockIdx.x * 256 + tid; idx < count; idx += MLP_BLOCKS * 256) {
        const int p = g_list[idx];
        const int b = p >> 16;
        const int pid = p & 0xFFFF;
        const int h = pid >> 8;
        const int w = pid & 255;
        const bool hm = h > 0, hp = h < 255, wm = w > 0, wp = w < 255;

        // ---- Perceive: y[64] as 32 x f32x2: (id,sx),(sy,lap) per channel ----
        ULL y2[32];
#pragma unroll
        for (int c = 0; c < 16; c++) {
            const float* xc = x + (size_t)(b * 16 + c) * HW + pid;
            float v00 = (hm && wm) ? __ldg(xc - 257) : 0.f;
            float v01 = hm         ? __ldg(xc - 256) : 0.f;
            float v02 = (hm && wp) ? __ldg(xc - 255) : 0.f;
            float v10 = wm         ? __ldg(xc - 1)   : 0.f;
            float v11 =              __ldg(xc);
            float v12 = wp         ? __ldg(xc + 1)   : 0.f;
            float v20 = (hp && wm) ? __ldg(xc + 255) : 0.f;
            float v21 = hp         ? __ldg(xc + 256) : 0.f;
            float v22 = (hp && wp) ? __ldg(xc + 257) : 0.f;
            float sx  = ((v02 - v00) + 2.f * (v12 - v10) + (v22 - v20)) * 0.125f;
            float sy  = ((v20 - v00) + 2.f * (v21 - v01) + (v22 - v02)) * 0.125f;
            float lap = v01 + v10 + v12 + v21 - 4.f * v11;
            y2[2 * c]     = pack2(v11, sx);
            y2[2 * c + 1] = pack2(sy, lap);
        }

        // ---- MLP: 64 -> 128 (relu) -> 16 ----
        ULL dx2[8];
#pragma unroll
        for (int j = 0; j < 8; j++) dx2[j] = 0ULL;

#pragma unroll 2
        for (int o = 0; o < 128; o++) {
            const ulonglong2* row = reinterpret_cast<const ulonglong2*>(&w1s[o * 32]);
            ULL a0 = 0ULL, a1 = 0ULL, a2 = 0ULL, a3 = 0ULL;
#pragma unroll
            for (int i = 0; i < 8; i++) {
                ulonglong2 q0 = row[2 * i];
                ulonglong2 q1 = row[2 * i + 1];
                a0 = fma2(q0.x, y2[4 * i + 0], a0);
                a1 = fma2(q0.y, y2[4 * i + 1], a1);
                a2 = fma2(q1.x, y2[4 * i + 2], a2);
                a3 = fma2(q1.y, y2[4 * i + 3], a3);
            }
            ULL s = add2(add2(a0, a1), add2(a2, a3));
            float slo, shi;
            unpack2(slo, shi, s);
            float hv = fmaxf(slo + shi + b1s[o], 0.f);
            ULL hp2 = pack2(hv, hv);
            const ulonglong2* wr = reinterpret_cast<const ulonglong2*>(&w2ts[o * 8]);
#pragma unroll
            for (int j = 0; j < 4; j++) {
                ulonglong2 q = wr[j];
                dx2[2 * j]     = fma2(q.x, hp2, dx2[2 * j]);
                dx2[2 * j + 1] = fma2(q.y, hp2, dx2[2 * j + 1]);
            }
        }

        // ---- x_new = x + dx (fire==1 for all listed pixels) ----
#pragma unroll
        for (int j = 0; j < 8; j++) {
            float d0, d1;
            unpack2(d0, d1, dx2[j]);
            int ch0 = 2 * j, ch1 = 2 * j + 1;
            float cen0, cen1, t;
            unpack2(cen0, t, y2[2 * ch0]);  // identity filter = center value
            unpack2(cen1, t, y2[2 * ch1]);
            float xn0 = cen0 + d0;
            float xn1 = cen1 + d1;
            out[(size_t)(b * 16 + ch0) * HW + pid] = xn0;
            out[(size_t)(b * 16 + ch1) * HW + pid] = xn1;
            if (j == 1)  // ch1 == 3: alpha
                g_alpha[(size_t)b * HW + pid] = xn1;
        }
    }
}

__global__ void __launch_bounds__(256) nca_life_kernel(
    const float* __restrict__ x, float* __restrict__ out)
{
    const int w = threadIdx.x;
    const int h = blockIdx.x;
    const int b = blockIdx.y;
    const int pid = h * 256 + w;

    const float* x3 = x + (size_t)(b * 16 + 3) * HW;
    const float* al = g_alpha + (size_t)b * HW;

    float pre = -1e30f, post = -1e30f;
#pragma unroll
    for (int dh = -1; dh <= 1; dh++) {
        int hh = h + dh;
        if (hh < 0 || hh > 255) continue;
#pragma unroll
        for (int dw = -1; dw <= 1; dw++) {
            int ww = w + dw;
            if (ww < 0 || ww > 255) continue;
            int q = hh * 256 + ww;
            pre  = fmaxf(pre,  __ldg(x3 + q));
            post = fmaxf(post, al[q]);
        }
    }

    if (!(pre > 0.1f && post > 0.1f)) {
#pragma unroll
        for (int c = 0; c < 16; c++)
            out[(size_t)(b * 16 + c) * HW + pid] = 0.f;
    }
}

extern "C" void kernel_launch(void* const* d_in, const int* in_sizes, int n_in,
                              void* d_out, int out_size)
{
    // Bind inputs by element count — all five distinct.
    const float* x  = nullptr; const float* rm = nullptr;
    const float* w1 = nullptr; const float* b1 = nullptr; const float* w2 = nullptr;
    for (int i = 0; i < n_in; i++) {
        switch (in_sizes[i]) {
            case 16777216: x  = (const float*)d_in[i]; break;
            case 1048576:  rm = (const float*)d_in[i]; break;
            case 8192:     w1 = (const float*)d_in[i]; break;
            case 2048:     w2 = (const float*)d_in[i]; break;
            case 128:      b1 = (const float*)d_in[i]; break;
            default: break;
        }
    }
    if (!x || !rm || !w1 || !b1 || !w2) return;
    float* out = (float*)d_out;

    dim3 grid(256, 16);
    nca_zero_kernel<<<1, 1>>>();
    nca_prep_kernel<<<grid, 256>>>(x, rm, out);
    nca_mlp_kernel<<<MLP_BLOCKS, 256>>>(x, w1, b1, w2, out);
    nca_life_kernel<<<grid, 256>>>(x, out);
}

// round 11
// speedup vs baseline: 1.5741x; 1.1794x over previous
#include <cuda_runtime.h>
#include <cstdint>

// NCA grow step — fire-sparsity compaction + persistent MLP with L1 prefetch.
//
//  zero:  reset compaction counter (graph-replay safe).
//  prep:  fire = rand_mask <= 0.5. Non-fired pixels: x_new = x -> out + alpha.
//         Fired pixels: ballot-compacted into g_list (~50% of 1M).
//  mlp:   persistent (296 blocks, 2/SM): grid-stride over g_list, FULL warps.
//         Prefetches the NEXT pixel's 3x3 stencil rows into L1 during the
//         current pixel's MLP to hide scattered-load latency (R9: mlp ran at
//         only ~68% of its FFMA floor; theory = exposed perceive latency).
//  life:  life = (maxpool3(x.a)>0.1)&(maxpool3(x_new.a)>0.1); zero dead pixels.

typedef unsigned long long ULL;

#define HW 65536  // 256*256

__device__ float g_alpha[16 * HW];   // x_new alpha scratch (4 MB)
__device__ int   g_list[16 * HW];    // fired pixel ids: b*65536 + pid (4 MB)
__device__ int   g_count;

__device__ __forceinline__ ULL pack2(float lo, float hi) {
    ULL r;
    asm("mov.b64 %0, {%1, %2};" : "=l"(r) : "f"(lo), "f"(hi));
    return r;
}
__device__ __forceinline__ void unpack2(float& lo, float& hi, ULL v) {
    asm("mov.b64 {%0, %1}, %2;" : "=f"(lo), "=f"(hi) : "l"(v));
}
__device__ __forceinline__ ULL fma2(ULL a, ULL b, ULL c) {
    ULL d;
    asm("fma.rn.f32x2 %0, %1, %2, %3;" : "=l"(d) : "l"(a), "l"(b), "l"(c));
    return d;
}
__device__ __forceinline__ ULL add2(ULL a, ULL b) {
    ULL d;
    asm("add.rn.f32x2 %0, %1, %2;" : "=l"(d) : "l"(a), "l"(b));
    return d;
}
__device__ __forceinline__ void pf_l1(const void* p) {
    asm volatile("prefetch.global.L1 [%0];" :: "l"(p));
}

__global__ void nca_zero_kernel() { g_count = 0; }

// ---- prep: handle non-fired pixels, compact fired pixel ids ----
__global__ void __launch_bounds__(256) nca_prep_kernel(
    const float* __restrict__ x, const float* __restrict__ rmask,
    float* __restrict__ out)
{
    const int w = threadIdx.x;
    const int h = blockIdx.x;
    const int b = blockIdx.y;
    const int pid = h * 256 + w;
    const int lane = w & 31;

    const bool fire = __ldg(rmask + (size_t)b * HW + pid) <= 0.5f;

    unsigned m = __ballot_sync(0xffffffffu, fire);
    int base = 0;
    if (lane == 0) base = atomicAdd(&g_count, __popc(m));
    base = __shfl_sync(0xffffffffu, base, 0);
    if (fire) {
        g_list[base + __popc(m & ((1u << lane) - 1u))] = b * HW + pid;
    } else {
        // x_new = x: copy through, record alpha
#pragma unroll
        for (int c = 0; c < 16; c++) {
            float v = __ldg(x + (size_t)(b * 16 + c) * HW + pid);
            out[(size_t)(b * 16 + c) * HW + pid] = v;
            if (c == 3) g_alpha[(size_t)b * HW + pid] = v;
        }
    }
}

// ---- mlp: persistent full-warp work on fired pixels only ----
#define MLP_BLOCKS 296  // 2 CTAs/SM x 148 SMs

__global__ void __launch_bounds__(256, 2) nca_mlp_kernel(
    const float* __restrict__ x,
    const float* __restrict__ w1, const float* __restrict__ b1,
    const float* __restrict__ w2, float* __restrict__ out)
{
    __shared__ __align__(16) ULL w1s[4096];   // [128 o][32 pairs of i]  (32 KB)
    __shared__ __align__(16) ULL w2ts[1024];  // [128 o][8 pairs of out-c] (8 KB)
    __shared__ float b1s[128];

    const int tid = threadIdx.x;

    const ULL* w1u = reinterpret_cast<const ULL*>(w1);
    for (int i = tid; i < 4096; i += 256) w1s[i] = w1u[i];
    if (tid < 128) b1s[tid] = b1[tid];
    for (int i = tid; i < 1024; i += 256) {
        int o = i >> 3, j = i & 7;
        w2ts[i] = pack2(w2[(2 * j) * 128 + o], w2[(2 * j + 1) * 128 + o]);
    }
    __syncthreads();

    const int count = g_count;
    const int stride = MLP_BLOCKS * 256;

    for (int idx = blockIdx.x * 256 + tid; idx < count; idx += stride) {
        const int p = __ldg(&g_list[idx]);
        const int b = p >> 16;
        const int pid = p & 0xFFFF;
        const int h = pid >> 8;
        const int w = pid & 255;
        const bool hm = h > 0, hp = h < 255, wm = w > 0, wp = w < 255;

        // ---- Perceive: y[64] as 32 x f32x2: (id,sx),(sy,lap) per channel ----
        ULL y2[32];
#pragma unroll
        for (int c = 0; c < 16; c++) {
            const float* xc = x + (size_t)(b * 16 + c) * HW + pid;
            float v00 = (hm && wm) ? __ldg(xc - 257) : 0.f;
            float v01 = hm         ? __ldg(xc - 256) : 0.f;
            float v02 = (hm && wp) ? __ldg(xc - 255) : 0.f;
            float v10 = wm         ? __ldg(xc - 1)   : 0.f;
            float v11 =              __ldg(xc);
            float v12 = wp         ? __ldg(xc + 1)   : 0.f;
            float v20 = (hp && wm) ? __ldg(xc + 255) : 0.f;
            float v21 = hp         ? __ldg(xc + 256) : 0.f;
            float v22 = (hp && wp) ? __ldg(xc + 257) : 0.f;
            float sx  = ((v02 - v00) + 2.f * (v12 - v10) + (v22 - v20)) * 0.125f;
            float sy  = ((v20 - v00) + 2.f * (v21 - v01) + (v22 - v02)) * 0.125f;
            float lap = v01 + v10 + v12 + v21 - 4.f * v11;
            y2[2 * c]     = pack2(v11, sx);
            y2[2 * c + 1] = pack2(sy, lap);
        }

        // ---- Prefetch next pixel's stencil rows into L1 (hidden under MLP) ----
        const int nidx = idx + stride;
        if (nidx < count) {
            const int pn = __ldg(&g_list[nidx]);
            const int npid = pn & 0xFFFF;
            const float* xb = x + (size_t)(pn >> 16) * 16 * HW + npid;
            const int up = (npid >= 256) ? -256 : 0;
            const int dn = (npid < HW - 256) ? 256 : 0;
#pragma unroll
            for (int c = 0; c < 16; c++) {
                const float* r = xb + (size_t)c * HW;
                pf_l1(r + up);
                pf_l1(r);
                pf_l1(r + dn);
            }
        }

        // ---- MLP: 64 -> 128 (relu) -> 16 ----
        ULL dx2[8];
#pragma unroll
        for (int j = 0; j < 8; j++) dx2[j] = 0ULL;

#pragma unroll 2
        for (int o = 0; o < 128; o++) {
            const ulonglong2* row = reinterpret_cast<const ulonglong2*>(&w1s[o * 32]);
            ULL a0 = 0ULL, a1 = 0ULL, a2 = 0ULL, a3 = 0ULL;
#pragma unroll
            for (int i = 0; i < 8; i++) {
                ulonglong2 q0 = row[2 * i];
                ulonglong2 q1 = row[2 * i + 1];
                a0 = fma2(q0.x, y2[4 * i + 0], a0);
                a1 = fma2(q0.y, y2[4 * i + 1], a1);
                a2 = fma2(q1.x, y2[4 * i + 2], a2);
                a3 = fma2(q1.y, y2[4 * i + 3], a3);
            }
            ULL s = add2(add2(a0, a1), add2(a2, a3));
            float slo, shi;
            unpack2(slo, shi, s);
            float hv = fmaxf(slo + shi + b1s[o], 0.f);
            ULL hp2 = pack2(hv, hv);
            const ulonglong2* wr = reinterpret_cast<const ulonglong2*>(&w2ts[o * 8]);
#pragma unroll
            for (int j = 0; j < 4; j++) {
                ulonglong2 q = wr[j];
                dx2[2 * j]     = fma2(q.x, hp2, dx2[2 * j]);
                dx2[2 * j + 1] = fma2(q.y, hp2, dx2[2 * j + 1]);
            }
        }

        // ---- x_new = x + dx (fire==1 for all listed pixels) ----
#pragma unroll
        for (int j = 0; j < 8; j++) {
            float d0, d1;
            unpack2(d0, d1, dx2[j]);
            int ch0 = 2 * j, ch1 = 2 * j + 1;
            float cen0, cen1, t;
            unpack2(cen0, t, y2[2 * ch0]);  // identity filter = center value
            unpack2(cen1, t, y2[2 * ch1]);
            float xn0 = cen0 + d0;
            float xn1 = cen1 + d1;
            out[(size_t)(b * 16 + ch0) * HW + pid] = xn0;
            out[(size_t)(b * 16 + ch1) * HW + pid] = xn1;
            if (j == 1)  // ch1 == 3: alpha
                g_alpha[(size_t)b * HW + pid] = xn1;
        }
    }
}

__global__ void __launch_bounds__(256) nca_life_kernel(
    const float* __restrict__ x, float* __restrict__ out)
{
    const int w = threadIdx.x;
    const int h = blockIdx.x;
    const int b = blockIdx.y;
    const int pid = h * 256 + w;

    const float* x3 = x + (size_t)(b * 16 + 3) * HW;
    const float* al = g_alpha + (size_t)b * HW;

    float pre = -1e30f, post = -1e30f;
#pragma unroll
    for (int dh = -1; dh <= 1; dh++) {
        int hh = h + dh;
        if (hh < 0 || hh > 255) continue;
#pragma unroll
        for (int dw = -1; dw <= 1; dw++) {
            int ww = w + dw;
            if (ww < 0 || ww > 255) continue;
            int q = hh * 256 + ww;
            pre  = fmaxf(pre,  __ldg(x3 + q));
            post = fmaxf(post, al[q]);
        }
    }

    if (!(pre > 0.1f && post > 0.1f)) {
#pragma unroll
        for (int c = 0; c < 16; c++)
            out[(size_t)(b * 16 + c) * HW + pid] = 0.f;
    }
}

extern "C" void kernel_launch(void* const* d_in, const int* in_sizes, int n_in,
                              void* d_out, int out_size)
{
    // Bind inputs by element count — all five distinct.
    const float* x  = nullptr; const float* rm = nullptr;
    const float* w1 = nullptr; const float* b1 = nullptr; const float* w2 = nullptr;
    for (int i = 0; i < n_in; i++) {
        switch (in_sizes[i]) {
            case 16777216: x  = (const float*)d_in[i]; break;
            case 1048576:  rm = (const float*)d_in[i]; break;
            case 8192:     w1 = (const float*)d_in[i]; break;
            case 2048:     w2 = (const float*)d_in[i]; break;
            case 128:      b1 = (const float*)d_in[i]; break;
            default: break;
        }
    }
    if (!x || !rm || !w1 || !b1 || !w2) return;
    float* out = (float*)d_out;

    dim3 grid(256, 16);
    nca_zero_kernel<<<1, 1>>>();
    nca_prep_kernel<<<grid, 256>>>(x, rm, out);
    nca_mlp_kernel<<<MLP_BLOCKS, 256>>>(x, w1, b1, w2, out);
    nca_life_kernel<<<grid, 256>>>(x, out);
}